// round 5
// baseline (speedup 1.0000x reference)
#include <cuda_runtime.h>
#include <cuda_bf16.h>
#include <stdint.h>

#define F 128
#define NMAX 100000
#define EMAX 1700000   // E + N self loops

// ---------------- scratch (alloc-free: __device__ globals) ----------------
__device__ float g_h[NMAX * F];                 // transformed features h = feat @ W
__device__ __nv_bfloat16 g_xh[NMAX * F];        // current layer input, bf16 hi
__device__ __nv_bfloat16 g_xl[NMAX * F];        // current layer input, bf16 lo
__device__ __nv_bfloat16 g_wh[3][F * F];        // W bf16 hi per layer
__device__ __nv_bfloat16 g_wl[3][F * F];        // W bf16 lo per layer
__device__ float g_asrc[NMAX];
__device__ float g_adst[NMAX];
__device__ int   g_deg[NMAX];
__device__ int   g_rowptr[NMAX + 1];
__device__ int   g_cursor[NMAX];
__device__ int   g_srcs[EMAX];                  // src indices sorted by dst (CSR)
__device__ int   g_bsum[256];                   // scan block sums
__device__ int   g_bpre[257];                   // scan block prefixes (+ total)

// ---------------- helpers ----------------
__device__ __forceinline__ uint32_t smem_u32(const void* p) {
    uint32_t a;
    asm("{ .reg .u64 t; cvta.to.shared.u64 t, %1; cvt.u32.u64 %0, t; }" : "=r"(a) : "l"(p));
    return a;
}
__device__ __forceinline__ void ldsm_x4(uint32_t* r, uint32_t addr) {
    asm volatile("ldmatrix.sync.aligned.m8n8.x4.shared.b16 {%0,%1,%2,%3}, [%4];"
                 : "=r"(r[0]), "=r"(r[1]), "=r"(r[2]), "=r"(r[3]) : "r"(addr));
}
__device__ __forceinline__ void ldsm_x4_t(uint32_t* r, uint32_t addr) {
    asm volatile("ldmatrix.sync.aligned.m8n8.x4.trans.shared.b16 {%0,%1,%2,%3}, [%4];"
                 : "=r"(r[0]), "=r"(r[1]), "=r"(r[2]), "=r"(r[3]) : "r"(addr));
}
__device__ __forceinline__ void mma_bf16(float* c, const uint32_t* a, const uint32_t* b) {
    asm volatile("mma.sync.aligned.m16n8k16.row.col.f32.bf16.bf16.f32 "
                 "{%0,%1,%2,%3}, {%4,%5,%6,%7}, {%8,%9}, {%0,%1,%2,%3};"
                 : "+f"(c[0]), "+f"(c[1]), "+f"(c[2]), "+f"(c[3])
                 : "r"(a[0]), "r"(a[1]), "r"(a[2]), "r"(a[3]), "r"(b[0]), "r"(b[1]));
}
__device__ __forceinline__ void split_bf16(float x, __nv_bfloat16& h, __nv_bfloat16& l) {
    h = __float2bfloat16_rn(x);
    l = __float2bfloat16_rn(x - __bfloat162float(h));
}
__device__ __forceinline__ void split4_store(float4 r, __nv_bfloat16* ph, __nv_bfloat16* pl) {
    __nv_bfloat16 h0, l0, h1, l1, h2, l2, h3, l3;
    split_bf16(r.x, h0, l0); split_bf16(r.y, h1, l1);
    split_bf16(r.z, h2, l2); split_bf16(r.w, h3, l3);
    uint2 hp, lp;
    hp.x = (uint32_t)__bfloat16_as_ushort(h0) | ((uint32_t)__bfloat16_as_ushort(h1) << 16);
    hp.y = (uint32_t)__bfloat16_as_ushort(h2) | ((uint32_t)__bfloat16_as_ushort(h3) << 16);
    lp.x = (uint32_t)__bfloat16_as_ushort(l0) | ((uint32_t)__bfloat16_as_ushort(l1) << 16);
    lp.y = (uint32_t)__bfloat16_as_ushort(l2) | ((uint32_t)__bfloat16_as_ushort(l3) << 16);
    *(uint2*)ph = hp;
    *(uint2*)pl = lp;
}

// ---------------- input / weight splitting ----------------
__global__ void k_split_x(const float* __restrict__ x, int total4) {
    int i = blockIdx.x * blockDim.x + threadIdx.x;
    if (i >= total4) return;
    float4 v = ((const float4*)x)[i];
    split4_store(v, &g_xh[i * 4], &g_xl[i * 4]);
}
__global__ void k_prepW(const float* __restrict__ W, int l) {
    int i = blockIdx.x * blockDim.x + threadIdx.x;
    if (i >= 4096) return;
    float4 v = ((const float4*)W)[i];
    split4_store(v, &g_wh[l][i * 4], &g_wl[l][i * 4]);
}

// ---------------- CSR build ----------------
__global__ void k_zero_deg(int N) {
    int i = blockIdx.x * blockDim.x + threadIdx.x;
    if (i < N) g_deg[i] = 0;
}
__global__ void k_count(const int* __restrict__ ei, int E, int N) {
    int j = blockIdx.x * blockDim.x + threadIdx.x;
    if (j >= E + N) return;
    int d = (j < E) ? ei[E + j] : (j - E);
    atomicAdd(&g_deg[d], 1);
}
__global__ void k_scan1(int N) {
    __shared__ int s[256];
    int t = threadIdx.x, b = blockIdx.x;
    int i0 = b * 1024 + t * 4;
    int sum = 0;
#pragma unroll
    for (int j = 0; j < 4; j++)
        if (i0 + j < N) sum += g_deg[i0 + j];
    s[t] = sum;
    __syncthreads();
#pragma unroll
    for (int off = 128; off; off >>= 1) {
        if (t < off) s[t] += s[t + off];
        __syncthreads();
    }
    if (t == 0) g_bsum[b] = s[0];
}
__global__ void k_scan2(int nb) {
    __shared__ int s[256];
    int t = threadIdx.x;
    int v = (t < nb) ? g_bsum[t] : 0;
    s[t] = v;
    __syncthreads();
#pragma unroll
    for (int off = 1; off < 256; off <<= 1) {
        int u = (t >= off) ? s[t - off] : 0;
        __syncthreads();
        s[t] += u;
        __syncthreads();
    }
    if (t <= nb) g_bpre[t] = (t == 0) ? 0 : s[t - 1];
    if (t == 255) g_bpre[256] = s[255];
}
__global__ void k_scan3(int N, int nb) {
    __shared__ int s[256];
    int t = threadIdx.x, b = blockIdx.x;
    int i0 = b * 1024 + t * 4;
    int d[4];
    int sum = 0;
#pragma unroll
    for (int j = 0; j < 4; j++) {
        d[j] = (i0 + j < N) ? g_deg[i0 + j] : 0;
        sum += d[j];
    }
    s[t] = sum;
    __syncthreads();
#pragma unroll
    for (int off = 1; off < 256; off <<= 1) {
        int u = (t >= off) ? s[t - off] : 0;
        __syncthreads();
        s[t] += u;
        __syncthreads();
    }
    int run = g_bpre[b] + s[t] - sum;
#pragma unroll
    for (int j = 0; j < 4; j++) {
        if (i0 + j < N) {
            g_rowptr[i0 + j] = run;
            g_cursor[i0 + j] = run;
        }
        run += d[j];
    }
    if (b == 0 && t == 0) g_rowptr[N] = g_bpre[nb];
}
__global__ void k_scatter(const int* __restrict__ ei, int E, int N) {
    int j = blockIdx.x * blockDim.x + threadIdx.x;
    if (j >= E + N) return;
    int sIdx, d;
    if (j < E) { sIdx = ei[j]; d = ei[E + j]; }
    else       { sIdx = j - E; d = j - E; }
    int pos = atomicAdd(&g_cursor[d], 1);
    g_srcs[pos] = sIdx;
}

// ---------------- bf16x3 tensor-core GEMM (mma.sync) + fused alpha dots ----------------
#define AS_STRIDE 136
#define TILE_B (128 * AS_STRIDE * 2)
#define OFF_AH 0
#define OFF_AL (TILE_B)
#define OFF_BH (2 * TILE_B)
#define OFF_BL (3 * TILE_B)
#define OFF_SAS (4 * TILE_B)
#define OFF_SAD (OFF_SAS + 512)
#define OFF_SUA (OFF_SAD + 512)
#define OFF_SUD (OFF_SUA + 512)
#define GEMM_SMEM (OFF_SUD + 512)

__global__ void __launch_bounds__(256)
k_gemm_mma(int layer, const float* __restrict__ av_s, const float* __restrict__ av_d, int Nn) {
    extern __shared__ char smem[];
    const uint32_t sb = smem_u32(smem);
    const int tid = threadIdx.x, lane = tid & 31, wid = tid >> 5;
    const int row0 = blockIdx.x * 128;

    float* s_as = (float*)(smem + OFF_SAS);
    float* s_ad = (float*)(smem + OFF_SAD);
    float* s_ua = (float*)(smem + OFF_SUA);
    float* s_ud = (float*)(smem + OFF_SUD);
    if (tid < 128) {
        s_as[tid] = av_s[tid];
        s_ad[tid] = av_d[tid];
        s_ua[tid] = 0.f;
        s_ud[tid] = 0.f;
    }

    {   // stage: pure copies (pre-split bf16 in global)
        int r = tid >> 1, seg = (tid & 1) * 64;
        int gr = min(row0 + r, Nn - 1);
        const uint4* sAh = (const uint4*)&g_xh[(size_t)gr * 128 + seg];
        const uint4* sAl = (const uint4*)&g_xl[(size_t)gr * 128 + seg];
        const uint4* sBh = (const uint4*)&g_wh[layer][r * 128 + seg];
        const uint4* sBl = (const uint4*)&g_wl[layer][r * 128 + seg];
        uint4* dAh = (uint4*)((__nv_bfloat16*)(smem + OFF_AH) + r * AS_STRIDE + seg);
        uint4* dAl = (uint4*)((__nv_bfloat16*)(smem + OFF_AL) + r * AS_STRIDE + seg);
        uint4* dBh = (uint4*)((__nv_bfloat16*)(smem + OFF_BH) + r * AS_STRIDE + seg);
        uint4* dBl = (uint4*)((__nv_bfloat16*)(smem + OFF_BL) + r * AS_STRIDE + seg);
#pragma unroll
        for (int j = 0; j < 8; j++) {
            dAh[j] = sAh[j];
            dAl[j] = sAl[j];
            dBh[j] = sBh[j];
            dBl[j] = sBl[j];
        }
    }
    __syncthreads();

    const int wm = wid & 3, wn = wid >> 2;
    const int wrow = wm * 32, wcol = wn * 64;
    float acc[2][8][4];
#pragma unroll
    for (int i = 0; i < 2; i++)
#pragma unroll
        for (int j = 0; j < 8; j++)
#pragma unroll
            for (int q = 0; q < 4; q++) acc[i][j][q] = 0.f;

    const int lr = lane & 15, lc = lane >> 4;
#pragma unroll
    for (int pass = 0; pass < 3; pass++) {
        uint32_t aoff = sb + ((pass == 1) ? OFF_AL : OFF_AH);
        uint32_t boff = sb + ((pass == 2) ? OFF_BL : OFF_BH);
#pragma unroll
        for (int ks = 0; ks < 8; ks++) {
            int k0 = ks * 16;
            uint32_t a[2][4], b[4][4];
#pragma unroll
            for (int mt = 0; mt < 2; mt++)
                ldsm_x4(a[mt], aoff + ((wrow + mt * 16 + lr) * AS_STRIDE + lc * 8 + k0) * 2);
#pragma unroll
            for (int ng = 0; ng < 4; ng++)
                ldsm_x4_t(b[ng], boff + ((k0 + lr) * AS_STRIDE + wcol + ng * 16 + lc * 8) * 2);
#pragma unroll
            for (int mt = 0; mt < 2; mt++)
#pragma unroll
                for (int nt = 0; nt < 8; nt++)
                    mma_bf16(acc[mt][nt], a[mt], &b[nt >> 1][(nt & 1) * 2]);
        }
    }

    float pa[4] = {0.f, 0.f, 0.f, 0.f}, pd[4] = {0.f, 0.f, 0.f, 0.f};
#pragma unroll
    for (int mt = 0; mt < 2; mt++) {
#pragma unroll
        for (int half = 0; half < 2; half++) {
            int rl = wrow + mt * 16 + half * 8 + (lane >> 2);
            int gr = row0 + rl;
            bool ok = gr < Nn;
#pragma unroll
            for (int nt = 0; nt < 8; nt++) {
                int cl = wcol + nt * 8 + (lane & 3) * 2;
                float v0 = acc[mt][nt][half * 2 + 0];
                float v1 = acc[mt][nt][half * 2 + 1];
                if (ok) *(float2*)&g_h[(size_t)gr * 128 + cl] = make_float2(v0, v1);
                pa[mt * 2 + half] += v0 * s_as[cl] + v1 * s_as[cl + 1];
                pd[mt * 2 + half] += v0 * s_ad[cl] + v1 * s_ad[cl + 1];
            }
        }
    }
#pragma unroll
    for (int i = 0; i < 4; i++) {
        int rl = wrow + (i >> 1) * 16 + (i & 1) * 8 + (lane >> 2);
        atomicAdd(&s_ua[rl], pa[i]);
        atomicAdd(&s_ud[rl], pd[i]);
    }
    __syncthreads();
    if (tid < 128 && row0 + tid < Nn) {
        g_asrc[row0 + tid] = s_ua[tid];
        g_adst[row0 + tid] = s_ud[tid];
    }
}

// ---------------- single-pass online-softmax aggregation, one warp per dst ----------------
__global__ void k_aggregate(const float* __restrict__ bias, float* __restrict__ outp,
                            int N, int write_final) {
    int warp = (blockIdx.x * blockDim.x + threadIdx.x) >> 5;
    int lane = threadIdx.x & 31;
    if (warp >= N) return;

    int beg = g_rowptr[warp];
    int end = g_rowptr[warp + 1];
    float ad = g_adst[warp];

    float m = -1e30f;       // running max (uniform across warp)
    float denom = 0.f;      // per-lane partial of sum(exp)
    float4 a0 = make_float4(0.f, 0.f, 0.f, 0.f);
    float4 a1 = a0, a2 = a0, a3 = a0;

    for (int base = beg; base < end; base += 32) {
        int e = base + lane;
        float v = -1e30f;
        int s = 0;
        if (e < end) {
            s = g_srcs[e];
            float t = g_asrc[s] + ad;
            v = t > 0.f ? t : 0.2f * t;
        }
        // batch max -> online rescale
        float bm = v;
#pragma unroll
        for (int off = 16; off; off >>= 1)
            bm = fmaxf(bm, __shfl_xor_sync(0xffffffffu, bm, off));
        float mn = fmaxf(m, bm);
        float scale = __expf(m - mn);   // first batch: exp(-huge) = 0, acc already 0
        m = mn;
        denom *= scale;
        a0.x *= scale; a0.y *= scale; a0.z *= scale; a0.w *= scale;
        a1.x *= scale; a1.y *= scale; a1.z *= scale; a1.w *= scale;
        a2.x *= scale; a2.y *= scale; a2.z *= scale; a2.w *= scale;
        a3.x *= scale; a3.y *= scale; a3.z *= scale; a3.w *= scale;

        float w = __expf(v - mn);       // invalid lanes: exp(-huge)=0
        denom += w;

        int cnt = min(32, end - base);
        int i = 0;
        // 4-way pipelined row gather: 4 independent loads in flight
        for (; i + 4 <= cnt; i += 4) {
            float w0 = __shfl_sync(0xffffffffu, w, i + 0);
            float w1 = __shfl_sync(0xffffffffu, w, i + 1);
            float w2 = __shfl_sync(0xffffffffu, w, i + 2);
            float w3 = __shfl_sync(0xffffffffu, w, i + 3);
            int   s0 = __shfl_sync(0xffffffffu, s, i + 0);
            int   s1 = __shfl_sync(0xffffffffu, s, i + 1);
            int   s2 = __shfl_sync(0xffffffffu, s, i + 2);
            int   s3 = __shfl_sync(0xffffffffu, s, i + 3);
            float4 r0 = *(const float4*)&g_h[(size_t)s0 * 128 + lane * 4];
            float4 r1 = *(const float4*)&g_h[(size_t)s1 * 128 + lane * 4];
            float4 r2 = *(const float4*)&g_h[(size_t)s2 * 128 + lane * 4];
            float4 r3 = *(const float4*)&g_h[(size_t)s3 * 128 + lane * 4];
            a0.x += w0 * r0.x; a0.y += w0 * r0.y; a0.z += w0 * r0.z; a0.w += w0 * r0.w;
            a1.x += w1 * r1.x; a1.y += w1 * r1.y; a1.z += w1 * r1.z; a1.w += w1 * r1.w;
            a2.x += w2 * r2.x; a2.y += w2 * r2.y; a2.z += w2 * r2.z; a2.w += w2 * r2.w;
            a3.x += w3 * r3.x; a3.y += w3 * r3.y; a3.z += w3 * r3.z; a3.w += w3 * r3.w;
        }
        for (; i < cnt; i++) {
            float wi = __shfl_sync(0xffffffffu, w, i);
            int   si = __shfl_sync(0xffffffffu, s, i);
            float4 r0 = *(const float4*)&g_h[(size_t)si * 128 + lane * 4];
            a0.x += wi * r0.x; a0.y += wi * r0.y; a0.z += wi * r0.z; a0.w += wi * r0.w;
        }
    }
    float4 acc;
    acc.x = (a0.x + a1.x) + (a2.x + a3.x);
    acc.y = (a0.y + a1.y) + (a2.y + a3.y);
    acc.z = (a0.z + a1.z) + (a2.z + a3.z);
    acc.w = (a0.w + a1.w) + (a2.w + a3.w);
#pragma unroll
    for (int off = 16; off; off >>= 1)
        denom += __shfl_xor_sync(0xffffffffu, denom, off);

    float inv = 1.f / denom;
    float4 bv = *(const float4*)&bias[lane * 4];
    float4 r;
    r.x = acc.x * inv + bv.x;
    r.y = acc.y * inv + bv.y;
    r.z = acc.z * inv + bv.z;
    r.w = acc.w * inv + bv.w;
    if (write_final) {
        *(float4*)&outp[(size_t)warp * 128 + lane * 4] = r;
    } else {
        r.x = r.x > 0.f ? r.x : expm1f(r.x);
        r.y = r.y > 0.f ? r.y : expm1f(r.y);
        r.z = r.z > 0.f ? r.z : expm1f(r.z);
        r.w = r.w > 0.f ? r.w : expm1f(r.w);
        size_t idx = (size_t)warp * 128 + lane * 4;
        split4_store(r, &g_xh[idx], &g_xl[idx]);
    }
}

// ---------------- launch ----------------
extern "C" void kernel_launch(void* const* d_in, const int* in_sizes, int n_in,
                              void* d_out, int out_size) {
    const float* x  = (const float*)d_in[0];
    const int*   ei = (const int*)d_in[1];
    int N  = in_sizes[0] / F;
    int E  = in_sizes[1] / 2;
    int ET = E + N;
    int nb = (N + 1023) / 1024;

    static int smem_set = 0;
    if (!smem_set) {
        cudaFuncSetAttribute(k_gemm_mma, cudaFuncAttributeMaxDynamicSharedMemorySize, GEMM_SMEM);
        smem_set = 1;
    }

    int warp_blocks = (N * 32 + 255) / 256;
    int gemm_blocks = (N + 127) / 128;

    k_split_x<<<(N * 32 + 255) / 256, 256>>>(x, N * 32);
    k_prepW<<<16, 256>>>((const float*)d_in[2], 0);
    k_prepW<<<16, 256>>>((const float*)d_in[6], 1);
    k_prepW<<<16, 256>>>((const float*)d_in[10], 2);
    k_zero_deg<<<(N + 255) / 256, 256>>>(N);
    k_count<<<(ET + 255) / 256, 256>>>(ei, E, N);
    k_scan1<<<nb, 256>>>(N);
    k_scan2<<<1, 256>>>(nb);
    k_scan3<<<nb, 256>>>(N, nb);
    k_scatter<<<(ET + 255) / 256, 256>>>(ei, E, N);

    for (int l = 0; l < 3; l++) {
        const float* as = (const float*)d_in[3 + 4 * l];
        const float* ad = (const float*)d_in[4 + 4 * l];
        const float* b  = (const float*)d_in[5 + 4 * l];
        k_gemm_mma<<<gemm_blocks, 256, GEMM_SMEM>>>(l, as, ad, N);
        k_aggregate<<<warp_blocks, 256>>>(b, l == 2 ? (float*)d_out : nullptr, N, l == 2 ? 1 : 0);
    }
}

// round 6
// speedup vs baseline: 1.0991x; 1.0991x over previous
#include <cuda_runtime.h>
#include <cuda_bf16.h>
#include <stdint.h>

#define F 128
#define NMAX 100000
#define EMAX 1700000   // E + N self loops

// ---------------- scratch (alloc-free: __device__ globals) ----------------
__device__ float g_h[NMAX * F];                 // transformed features h = feat @ W
__device__ __nv_bfloat16 g_xh[NMAX * F];        // current layer input, bf16 hi
__device__ __nv_bfloat16 g_xl[NMAX * F];        // current layer input, bf16 lo
__device__ __nv_bfloat16 g_wh[3][F * F];        // W bf16 hi per layer
__device__ __nv_bfloat16 g_wl[3][F * F];        // W bf16 lo per layer
__device__ float g_asrc[NMAX];
__device__ float g_adst[NMAX];
__device__ int   g_deg[NMAX];
__device__ int   g_rowptr[NMAX + 1];
__device__ int   g_cursor[NMAX];
__device__ int   g_srcs[EMAX];                  // src indices sorted by dst (CSR)
__device__ int   g_bsum[256];                   // scan block sums
__device__ int   g_bpre[257];                   // scan block prefixes (+ total)

// ---------------- helpers ----------------
__device__ __forceinline__ uint32_t smem_u32(const void* p) {
    uint32_t a;
    asm("{ .reg .u64 t; cvta.to.shared.u64 t, %1; cvt.u32.u64 %0, t; }" : "=r"(a) : "l"(p));
    return a;
}
__device__ __forceinline__ void ldsm_x4(uint32_t* r, uint32_t addr) {
    asm volatile("ldmatrix.sync.aligned.m8n8.x4.shared.b16 {%0,%1,%2,%3}, [%4];"
                 : "=r"(r[0]), "=r"(r[1]), "=r"(r[2]), "=r"(r[3]) : "r"(addr));
}
__device__ __forceinline__ void ldsm_x4_t(uint32_t* r, uint32_t addr) {
    asm volatile("ldmatrix.sync.aligned.m8n8.x4.trans.shared.b16 {%0,%1,%2,%3}, [%4];"
                 : "=r"(r[0]), "=r"(r[1]), "=r"(r[2]), "=r"(r[3]) : "r"(addr));
}
__device__ __forceinline__ void mma_bf16(float* c, const uint32_t* a, const uint32_t* b) {
    asm volatile("mma.sync.aligned.m16n8k16.row.col.f32.bf16.bf16.f32 "
                 "{%0,%1,%2,%3}, {%4,%5,%6,%7}, {%8,%9}, {%0,%1,%2,%3};"
                 : "+f"(c[0]), "+f"(c[1]), "+f"(c[2]), "+f"(c[3])
                 : "r"(a[0]), "r"(a[1]), "r"(a[2]), "r"(a[3]), "r"(b[0]), "r"(b[1]));
}
__device__ __forceinline__ void split_bf16(float x, __nv_bfloat16& h, __nv_bfloat16& l) {
    h = __float2bfloat16_rn(x);
    l = __float2bfloat16_rn(x - __bfloat162float(h));
}
__device__ __forceinline__ void split4_store(float4 r, __nv_bfloat16* ph, __nv_bfloat16* pl) {
    __nv_bfloat16 h0, l0, h1, l1, h2, l2, h3, l3;
    split_bf16(r.x, h0, l0); split_bf16(r.y, h1, l1);
    split_bf16(r.z, h2, l2); split_bf16(r.w, h3, l3);
    uint2 hp, lp;
    hp.x = (uint32_t)__bfloat16_as_ushort(h0) | ((uint32_t)__bfloat16_as_ushort(h1) << 16);
    hp.y = (uint32_t)__bfloat16_as_ushort(h2) | ((uint32_t)__bfloat16_as_ushort(h3) << 16);
    lp.x = (uint32_t)__bfloat16_as_ushort(l0) | ((uint32_t)__bfloat16_as_ushort(l1) << 16);
    lp.y = (uint32_t)__bfloat16_as_ushort(l2) | ((uint32_t)__bfloat16_as_ushort(l3) << 16);
    *(uint2*)ph = hp;
    *(uint2*)pl = lp;
}

// ---------------- input / weight splitting ----------------
__global__ void k_split_x(const float* __restrict__ x, int total4) {
    int i = blockIdx.x * blockDim.x + threadIdx.x;
    if (i >= total4) return;
    float4 v = ((const float4*)x)[i];
    split4_store(v, &g_xh[i * 4], &g_xl[i * 4]);
}
__global__ void k_prepW_all(const float* __restrict__ W0, const float* __restrict__ W1,
                            const float* __restrict__ W2) {
    int i = blockIdx.x * blockDim.x + threadIdx.x;    // 3*4096 float4s
    if (i >= 3 * 4096) return;
    int l = i >> 12, j = i & 4095;
    const float* W = (l == 0) ? W0 : (l == 1) ? W1 : W2;
    float4 v = ((const float4*)W)[j];
    split4_store(v, &g_wh[l][j * 4], &g_wl[l][j * 4]);
}

// ---------------- CSR build ----------------
__global__ void k_zero_deg(int N) {
    int i = blockIdx.x * blockDim.x + threadIdx.x;
    if (i < N) g_deg[i] = 0;
}
__global__ void k_count(const int* __restrict__ ei, int E, int N) {
    int j = blockIdx.x * blockDim.x + threadIdx.x;
    if (j >= E + N) return;
    int d = (j < E) ? ei[E + j] : (j - E);
    atomicAdd(&g_deg[d], 1);
}
__global__ void k_scan1(int N) {
    __shared__ int s[256];
    int t = threadIdx.x, b = blockIdx.x;
    int i0 = b * 1024 + t * 4;
    int sum = 0;
#pragma unroll
    for (int j = 0; j < 4; j++)
        if (i0 + j < N) sum += g_deg[i0 + j];
    s[t] = sum;
    __syncthreads();
#pragma unroll
    for (int off = 128; off; off >>= 1) {
        if (t < off) s[t] += s[t + off];
        __syncthreads();
    }
    if (t == 0) g_bsum[b] = s[0];
}
__global__ void k_scan2(int nb) {
    __shared__ int s[256];
    int t = threadIdx.x;
    int v = (t < nb) ? g_bsum[t] : 0;
    s[t] = v;
    __syncthreads();
#pragma unroll
    for (int off = 1; off < 256; off <<= 1) {
        int u = (t >= off) ? s[t - off] : 0;
        __syncthreads();
        s[t] += u;
        __syncthreads();
    }
    if (t <= nb) g_bpre[t] = (t == 0) ? 0 : s[t - 1];
    if (t == 255) g_bpre[256] = s[255];
}
__global__ void k_scan3(int N, int nb) {
    __shared__ int s[256];
    int t = threadIdx.x, b = blockIdx.x;
    int i0 = b * 1024 + t * 4;
    int d[4];
    int sum = 0;
#pragma unroll
    for (int j = 0; j < 4; j++) {
        d[j] = (i0 + j < N) ? g_deg[i0 + j] : 0;
        sum += d[j];
    }
    s[t] = sum;
    __syncthreads();
#pragma unroll
    for (int off = 1; off < 256; off <<= 1) {
        int u = (t >= off) ? s[t - off] : 0;
        __syncthreads();
        s[t] += u;
        __syncthreads();
    }
    int run = g_bpre[b] + s[t] - sum;
#pragma unroll
    for (int j = 0; j < 4; j++) {
        if (i0 + j < N) {
            g_rowptr[i0 + j] = run;
            g_cursor[i0 + j] = run;
        }
        run += d[j];
    }
    if (b == 0 && t == 0) g_rowptr[N] = g_bpre[nb];
}
__global__ void k_scatter(const int* __restrict__ ei, int E, int N) {
    int j = blockIdx.x * blockDim.x + threadIdx.x;
    if (j >= E + N) return;
    int sIdx, d;
    if (j < E) { sIdx = ei[j]; d = ei[E + j]; }
    else       { sIdx = j - E; d = j - E; }
    int pos = atomicAdd(&g_cursor[d], 1);
    g_srcs[pos] = sIdx;
}

// ---------------- bf16x3 tensor-core GEMM (mma.sync) + fused alpha dots ----------------
#define AS_STRIDE 136
#define TILE_B (128 * AS_STRIDE * 2)
#define OFF_AH 0
#define OFF_AL (TILE_B)
#define OFF_BH (2 * TILE_B)
#define OFF_BL (3 * TILE_B)
#define OFF_SAS (4 * TILE_B)
#define OFF_SAD (OFF_SAS + 512)
#define OFF_SUA (OFF_SAD + 512)
#define OFF_SUD (OFF_SUA + 512)
#define GEMM_SMEM (OFF_SUD + 512)

__global__ void __launch_bounds__(256)
k_gemm_mma(int layer, const float* __restrict__ av_s, const float* __restrict__ av_d, int Nn) {
    extern __shared__ char smem[];
    const uint32_t sb = smem_u32(smem);
    const int tid = threadIdx.x, lane = tid & 31, wid = tid >> 5;
    const int row0 = blockIdx.x * 128;

    float* s_as = (float*)(smem + OFF_SAS);
    float* s_ad = (float*)(smem + OFF_SAD);
    float* s_ua = (float*)(smem + OFF_SUA);
    float* s_ud = (float*)(smem + OFF_SUD);
    if (tid < 128) {
        s_as[tid] = av_s[tid];
        s_ad[tid] = av_d[tid];
        s_ua[tid] = 0.f;
        s_ud[tid] = 0.f;
    }

    {   // stage: pure copies (pre-split bf16 in global)
        int r = tid >> 1, seg = (tid & 1) * 64;
        int gr = min(row0 + r, Nn - 1);
        const uint4* sAh = (const uint4*)&g_xh[(size_t)gr * 128 + seg];
        const uint4* sAl = (const uint4*)&g_xl[(size_t)gr * 128 + seg];
        const uint4* sBh = (const uint4*)&g_wh[layer][r * 128 + seg];
        const uint4* sBl = (const uint4*)&g_wl[layer][r * 128 + seg];
        uint4* dAh = (uint4*)((__nv_bfloat16*)(smem + OFF_AH) + r * AS_STRIDE + seg);
        uint4* dAl = (uint4*)((__nv_bfloat16*)(smem + OFF_AL) + r * AS_STRIDE + seg);
        uint4* dBh = (uint4*)((__nv_bfloat16*)(smem + OFF_BH) + r * AS_STRIDE + seg);
        uint4* dBl = (uint4*)((__nv_bfloat16*)(smem + OFF_BL) + r * AS_STRIDE + seg);
#pragma unroll
        for (int j = 0; j < 8; j++) {
            dAh[j] = sAh[j];
            dAl[j] = sAl[j];
            dBh[j] = sBh[j];
            dBl[j] = sBl[j];
        }
    }
    __syncthreads();

    const int wm = wid & 3, wn = wid >> 2;
    const int wrow = wm * 32, wcol = wn * 64;
    float acc[2][8][4];
#pragma unroll
    for (int i = 0; i < 2; i++)
#pragma unroll
        for (int j = 0; j < 8; j++)
#pragma unroll
            for (int q = 0; q < 4; q++) acc[i][j][q] = 0.f;

    const int lr = lane & 15, lc = lane >> 4;
#pragma unroll
    for (int pass = 0; pass < 3; pass++) {
        uint32_t aoff = sb + ((pass == 1) ? OFF_AL : OFF_AH);
        uint32_t boff = sb + ((pass == 2) ? OFF_BL : OFF_BH);
#pragma unroll
        for (int ks = 0; ks < 8; ks++) {
            int k0 = ks * 16;
            uint32_t a[2][4], b[4][4];
#pragma unroll
            for (int mt = 0; mt < 2; mt++)
                ldsm_x4(a[mt], aoff + ((wrow + mt * 16 + lr) * AS_STRIDE + lc * 8 + k0) * 2);
#pragma unroll
            for (int ng = 0; ng < 4; ng++)
                ldsm_x4_t(b[ng], boff + ((k0 + lr) * AS_STRIDE + wcol + ng * 16 + lc * 8) * 2);
#pragma unroll
            for (int mt = 0; mt < 2; mt++)
#pragma unroll
                for (int nt = 0; nt < 8; nt++)
                    mma_bf16(acc[mt][nt], a[mt], &b[nt >> 1][(nt & 1) * 2]);
        }
    }

    float pa[4] = {0.f, 0.f, 0.f, 0.f}, pd[4] = {0.f, 0.f, 0.f, 0.f};
#pragma unroll
    for (int mt = 0; mt < 2; mt++) {
#pragma unroll
        for (int half = 0; half < 2; half++) {
            int rl = wrow + mt * 16 + half * 8 + (lane >> 2);
            int gr = row0 + rl;
            bool ok = gr < Nn;
#pragma unroll
            for (int nt = 0; nt < 8; nt++) {
                int cl = wcol + nt * 8 + (lane & 3) * 2;
                float v0 = acc[mt][nt][half * 2 + 0];
                float v1 = acc[mt][nt][half * 2 + 1];
                if (ok) *(float2*)&g_h[(size_t)gr * 128 + cl] = make_float2(v0, v1);
                pa[mt * 2 + half] += v0 * s_as[cl] + v1 * s_as[cl + 1];
                pd[mt * 2 + half] += v0 * s_ad[cl] + v1 * s_ad[cl + 1];
            }
        }
    }
#pragma unroll
    for (int i = 0; i < 4; i++) {
        int rl = wrow + (i >> 1) * 16 + (i & 1) * 8 + (lane >> 2);
        atomicAdd(&s_ua[rl], pa[i]);
        atomicAdd(&s_ud[rl], pd[i]);
    }
    __syncthreads();
    if (tid < 128 && row0 + tid < Nn) {
        g_asrc[row0 + tid] = s_ua[tid];
        g_adst[row0 + tid] = s_ud[tid];
    }
}

// ---------------- two-pass softmax aggregation (R4 form), one warp per dst ----------------
__global__ void k_aggregate(const float* __restrict__ bias, float* __restrict__ outp,
                            int N, int write_final) {
    int warp = (blockIdx.x * blockDim.x + threadIdx.x) >> 5;
    int lane = threadIdx.x & 31;
    if (warp >= N) return;

    int beg = g_rowptr[warp];
    int end = g_rowptr[warp + 1];
    float ad = g_adst[warp];

    // pass 1: segment max
    float m = -1e30f;
    for (int e = beg + lane; e < end; e += 32) {
        int s = __ldg(&g_srcs[e]);
        float v = __ldg(&g_asrc[s]) + ad;
        v = v > 0.f ? v : 0.2f * v;
        m = fmaxf(m, v);
    }
#pragma unroll
    for (int off = 16; off; off >>= 1)
        m = fmaxf(m, __shfl_xor_sync(0xffffffffu, m, off));

    // pass 2: unnormalized weighted sum
    float4 acc = make_float4(0.f, 0.f, 0.f, 0.f);
    float denom = 0.f;
    for (int base = beg; base < end; base += 32) {
        int e = base + lane;
        float w = 0.f;
        int s = 0;
        if (e < end) {
            s = __ldg(&g_srcs[e]);
            float v = __ldg(&g_asrc[s]) + ad;
            v = v > 0.f ? v : 0.2f * v;
            w = __expf(v - m);
        }
        denom += w;
        int cnt = min(32, end - base);
        for (int i = 0; i < cnt; i++) {
            float wi = __shfl_sync(0xffffffffu, w, i);
            int   si = __shfl_sync(0xffffffffu, s, i);
            float4 hv = __ldg((const float4*)&g_h[(size_t)si * 128 + lane * 4]);
            acc.x += wi * hv.x; acc.y += wi * hv.y;
            acc.z += wi * hv.z; acc.w += wi * hv.w;
        }
    }
#pragma unroll
    for (int off = 16; off; off >>= 1)
        denom += __shfl_xor_sync(0xffffffffu, denom, off);

    float inv = 1.f / denom;
    float4 bv = *(const float4*)&bias[lane * 4];
    float4 r;
    r.x = acc.x * inv + bv.x;
    r.y = acc.y * inv + bv.y;
    r.z = acc.z * inv + bv.z;
    r.w = acc.w * inv + bv.w;
    if (write_final) {
        *(float4*)&outp[(size_t)warp * 128 + lane * 4] = r;
    } else {
        r.x = r.x > 0.f ? r.x : expm1f(r.x);
        r.y = r.y > 0.f ? r.y : expm1f(r.y);
        r.z = r.z > 0.f ? r.z : expm1f(r.z);
        r.w = r.w > 0.f ? r.w : expm1f(r.w);
        size_t idx = (size_t)warp * 128 + lane * 4;
        split4_store(r, &g_xh[idx], &g_xl[idx]);
    }
}

// ---------------- launch ----------------
extern "C" void kernel_launch(void* const* d_in, const int* in_sizes, int n_in,
                              void* d_out, int out_size) {
    const float* x  = (const float*)d_in[0];
    const int*   ei = (const int*)d_in[1];
    int N  = in_sizes[0] / F;
    int E  = in_sizes[1] / 2;
    int ET = E + N;
    int nb = (N + 1023) / 1024;

    static int smem_set = 0;
    if (!smem_set) {
        cudaFuncSetAttribute(k_gemm_mma, cudaFuncAttributeMaxDynamicSharedMemorySize, GEMM_SMEM);
        smem_set = 1;
    }

    int warp_blocks = (N * 32 + 255) / 256;
    int gemm_blocks = (N + 127) / 128;

    // launch #4 = k_gemm_mma (ncu captures the 4th launch)
    k_split_x<<<(N * 32 + 255) / 256, 256>>>(x, N * 32);
    k_prepW_all<<<48, 256>>>((const float*)d_in[2], (const float*)d_in[6], (const float*)d_in[10]);
    k_zero_deg<<<(N + 255) / 256, 256>>>(N);
    k_gemm_mma<<<gemm_blocks, 256, GEMM_SMEM>>>(0, (const float*)d_in[3], (const float*)d_in[4], N);
    k_count<<<(ET + 255) / 256, 256>>>(ei, E, N);
    k_scan1<<<nb, 256>>>(N);
    k_scan2<<<1, 256>>>(nb);
    k_scan3<<<nb, 256>>>(N, nb);
    k_scatter<<<(ET + 255) / 256, 256>>>(ei, E, N);

    for (int l = 0; l < 3; l++) {
        const float* as = (const float*)d_in[3 + 4 * l];
        const float* ad = (const float*)d_in[4 + 4 * l];
        const float* b  = (const float*)d_in[5 + 4 * l];
        if (l > 0)
            k_gemm_mma<<<gemm_blocks, 256, GEMM_SMEM>>>(l, as, ad, N);
        k_aggregate<<<warp_blocks, 256>>>(b, l == 2 ? (float*)d_out : nullptr, N, l == 2 ? 1 : 0);
    }
}